// round 12
// baseline (speedup 1.0000x reference)
#include <cuda_runtime.h>
#include <cuda_fp16.h>
#include <cstdint>

// ---------------------------------------------------------------------------
// Problem constants
// ---------------------------------------------------------------------------
#define M_TOK   4096
#define K_IN    4096
#define N_OUT   11008
#define GROUPSZ 128

// GEMM tiling: 4 warps (2Mx2N), warp tile 64x64, raw mma.sync, 4-stage ring
#define BM      128
#define BN      128
#define BK      64
#define NITER   (K_IN / BK)        // 64
#define NTHREADS 128
#define NSTAGE  4

#define A_LD    72                 // 64 + 8 pad (halves); 144B row stride
#define A_STAGE_BYTES (BM * A_LD * 2)          // 18432
#define BQ_STAGE_BYTES (8 * BN * 4)            // 8 kp-rows x 128 words = 4096
#define STAGE_BYTES   (A_STAGE_BYTES + BQ_STAGE_BYTES)  // 22528
#define SMEM_DYN      (NSTAGE * STAGE_BYTES)            // 90112 (x2 CTAs = 176KB)

// fp16 x scratch (no allocations allowed)
__device__ __half g_Xh[(size_t)M_TOK * K_IN];

// ---------------------------------------------------------------------------
// Kernel 0: convert x f32 -> f16 (harness materializes jax f16 as f32)
// ---------------------------------------------------------------------------
__global__ void convert_x_kernel(const float* __restrict__ x)
{
    size_t i = ((size_t)blockIdx.x * blockDim.x + threadIdx.x) * 4;
    if (i >= (size_t)M_TOK * K_IN) return;
    float4 v = *(const float4*)(x + i);
    *(__half2*)(g_Xh + i)     = __floats2half2_rn(v.x, v.y);
    *(__half2*)(g_Xh + i + 2) = __floats2half2_rn(v.z, v.w);
}

// ---------------------------------------------------------------------------
// helpers
// ---------------------------------------------------------------------------
__device__ __forceinline__ uint32_t smem_u32(const void* p) {
    uint32_t a;
    asm("{ .reg .u64 t; cvta.to.shared.u64 t, %1; cvt.u32.u64 %0, t; }"
        : "=r"(a) : "l"(p));
    return a;
}
__device__ __forceinline__ void cp_async16(uint32_t saddr, const void* gaddr) {
    asm volatile("cp.async.ca.shared.global [%0], [%1], 16;\n"
                 :: "r"(saddr), "l"(gaddr));
}
#define CP_COMMIT() asm volatile("cp.async.commit_group;\n" ::: "memory")
#define CP_WAIT2()  asm volatile("cp.async.wait_group 2;\n" ::: "memory")

__device__ __forceinline__ void ldsm_x4(uint32_t& r0, uint32_t& r1,
                                        uint32_t& r2, uint32_t& r3, uint32_t addr) {
    asm volatile("ldmatrix.sync.aligned.m8n8.x4.shared.b16 {%0,%1,%2,%3}, [%4];"
                 : "=r"(r0), "=r"(r1), "=r"(r2), "=r"(r3) : "r"(addr));
}
__device__ __forceinline__ void mma16816(float* d, const uint32_t* a,
                                         uint32_t b0, uint32_t b1) {
    asm volatile(
        "mma.sync.aligned.m16n8k16.row.col.f32.f16.f16.f32 "
        "{%0,%1,%2,%3}, {%4,%5,%6,%7}, {%8,%9}, {%0,%1,%2,%3};"
        : "+f"(d[0]), "+f"(d[1]), "+f"(d[2]), "+f"(d[3])
        : "r"(a[0]), "r"(a[1]), "r"(a[2]), "r"(a[3]), "r"(b0), "r"(b1));
}

// ---------------------------------------------------------------------------
// Fused 4-bit dequant + HMMA GEMM:  C[M,N] = X[M,K] * dequant(Q)[K,N] + bias
//
// B is staged in SMEM as RAW packed int32 (4KB/stage, via cp.async) and
// dequantized directly into mma.sync B fragments at consume time:
//   thread (t=lane%4, g=lane/4) needs k=2t,2t+1 (and +8) at col n,
//   which are adjacent nibbles of words Bq[2*kt + {0,1}][n].
// fp16 magic: fp16(0x6400|q) = 1024+q exact, (u-(1024+z))*s bit-exact.
// Per-n zero/scale half2 broadcasts live in regs, prefetched 1 stage ahead.
// ---------------------------------------------------------------------------
__global__ void __launch_bounds__(NTHREADS, 2)
gemm_q4_kernel(const int* __restrict__ qweight,
               const int* __restrict__ qzeros,
               const float* __restrict__ scales,
               const float* __restrict__ bias,
               float* __restrict__ out)
{
    extern __shared__ __align__(16) char smem[];
    const uint32_t sbase = smem_u32(smem);

    const int tid  = threadIdx.x;
    const int warp = tid >> 5;
    const int lane = tid & 31;
    const int gl   = lane >> 2;         // n within 8-col group
    const int tq   = lane & 3;          // k quad
    const int sh   = tq * 8;            // nibble shift for k=2t
    const int bm   = blockIdx.x * BM;   // M fastest: A + qweight stay L2-resident
    const int bn   = blockIdx.y * BN;

    // warp tile 64x64, grid 2(M) x 2(N)
    const int wm = (warp >> 1) * 64;
    const int wn = (warp & 1) * 64;

    const __half* Xb = g_Xh + (size_t)bm * K_IN;

    float acc[4][8][4];
    #pragma unroll
    for (int mi = 0; mi < 4; mi++)
        #pragma unroll
        for (int nt = 0; nt < 8; nt++)
            #pragma unroll
            for (int e = 0; e < 4; e++)
                acc[mi][nt][e] = 0.0f;

    // group constants (per thread: 8 n-columns = gl + 8*nt)
    __half2 hz[8], hs[8];
    uint32_t zr[8];
    float    sraw[8];

    auto load_group_raw = [&](int g) {
        const uint32_t* qz = (const uint32_t*)qzeros
                           + (size_t)g * (N_OUT / 8) + ((bn + wn) >> 3);
        *(uint4*)zr       = *(const uint4*)qz;
        *(uint4*)(zr + 4) = *(const uint4*)(qz + 4);
        const float* sp = scales + (size_t)g * N_OUT + bn + wn + gl;
        #pragma unroll
        for (int i = 0; i < 8; i++)
            sraw[i] = sp[8 * i];
    };
    auto convert_group = [&]() {
        #pragma unroll
        for (int nt = 0; nt < 8; nt++) {
            uint32_t z = ((zr[nt] >> (gl * 4)) & 15u) + 1u + 0x6400u;
            uint32_t p = z | (z << 16);
            hz[nt] = *(__half2*)&p;
            hs[nt] = __half2half2(__float2half_rn(sraw[nt]));
        }
    };
    auto issue_a = [&](int ks, int buf) {
        const uint32_t abase = sbase + buf * STAGE_BYTES;
        const int k0 = ks * BK;
        #pragma unroll
        for (int i = 0; i < 8; i++) {
            int c = tid + NTHREADS * i;
            int row = c >> 3, cc = c & 7;
            cp_async16(abase + (uint32_t)(row * A_LD + cc * 8) * 2,
                       Xb + (size_t)row * K_IN + k0 + cc * 8);
        }
    };
    auto issue_bq = [&](int ks, int buf) {
        const uint32_t bqbase = sbase + buf * STAGE_BYTES + A_STAGE_BYTES;
        #pragma unroll
        for (int i = 0; i < 2; i++) {
            int c = tid + NTHREADS * i;          // 0..255
            int kp = c >> 5, cw = (c & 31) * 4;  // word col
            cp_async16(bqbase + (uint32_t)(kp * (BN * 4) + cw * 4),
                       qweight + (size_t)(ks * 8 + kp) * N_OUT + bn + cw);
        }
    };

    // ---- prologue: stages 0,1 in flight; group 0 constants ready ----
    issue_a(0, 0); issue_bq(0, 0); CP_COMMIT();
    issue_a(1, 1); issue_bq(1, 1); CP_COMMIT();
    load_group_raw(0);
    convert_group();

    // per-lane bases
    const uint32_t a_lane = (uint32_t)(((wm + (lane & 15)) * A_LD + (lane >> 4) * 8) * 2);
    const uint32_t b_lane = (uint32_t)((wn + gl) * 4);

    for (int ks = 0; ks < NITER; ks++) {
        const int buf = ks & (NSTAGE - 1);

        if (ks + 2 < NITER) {
            const int nbuf = (ks + 2) & (NSTAGE - 1);
            issue_a(ks + 2, nbuf);     // buffer of stage ks-2: safe (barrier ks-1)
            issue_bq(ks + 2, nbuf);
        }
        CP_COMMIT();

        if (ks & 1) {
            if (ks + 1 < NITER) load_group_raw((ks + 1) >> 1);
        } else if (ks) {
            convert_group();           // group ks>>1 (raw loaded at ks-1)
        }

        CP_WAIT2();                    // stage-ks group (committed 2 iters ago)
        __syncthreads();               // cross-thread visibility + buffer reuse

        const uint32_t abase  = sbase + buf * STAGE_BYTES + a_lane;
        const uint32_t bqbase = sbase + buf * STAGE_BYTES + A_STAGE_BYTES + b_lane;

        #pragma unroll
        for (int kt = 0; kt < 4; kt++) {
            uint32_t a[4][4];
            #pragma unroll
            for (int mi = 0; mi < 4; mi++)
                ldsm_x4(a[mi][0], a[mi][1], a[mi][2], a[mi][3],
                        abase + (uint32_t)(mi * 16 * A_LD * 2 + kt * 32));
            const uint32_t r0 = bqbase + (uint32_t)((2 * kt) * (BN * 4));
            #pragma unroll
            for (int nt = 0; nt < 8; nt++) {
                uint32_t w0 = *(const uint32_t*)(smem + (r0 - sbase) + nt * 32);
                uint32_t w1 = *(const uint32_t*)(smem + (r0 - sbase) + BN * 4 + nt * 32);
                uint32_t v0 = w0 >> sh;
                uint32_t v1 = w1 >> sh;
                uint32_t u0 = (v0 & 0xFu) | ((v0 << 12) & 0xF0000u) | 0x64006400u;
                uint32_t u1 = (v1 & 0xFu) | ((v1 << 12) & 0xF0000u) | 0x64006400u;
                __half2 h0 = __hmul2(__hsub2(*(__half2*)&u0, hz[nt]), hs[nt]);
                __half2 h1 = __hmul2(__hsub2(*(__half2*)&u1, hz[nt]), hs[nt]);
                uint32_t b0 = *(uint32_t*)&h0;
                uint32_t b1 = *(uint32_t*)&h1;
                #pragma unroll
                for (int mi = 0; mi < 4; mi++)
                    mma16816(acc[mi][nt], a[mi][0] ? a[mi] : a[mi], b0, b1);
            }
        }
    }

    // ---- epilogue: direct float2 stores from mma d-frags (+bias) ----
    #pragma unroll
    for (int nt = 0; nt < 8; nt++) {
        const int col = bn + wn + nt * 8 + tq * 2;
        float2 bb = *(const float2*)(bias + col);
        #pragma unroll
        for (int mi = 0; mi < 4; mi++) {
            const int row0 = bm + wm + mi * 16 + gl;
            float2 v0 = make_float2(acc[mi][nt][0] + bb.x, acc[mi][nt][1] + bb.y);
            float2 v1 = make_float2(acc[mi][nt][2] + bb.x, acc[mi][nt][3] + bb.y);
            *(float2*)(out + (size_t)row0 * N_OUT + col)       = v0;
            *(float2*)(out + (size_t)(row0 + 8) * N_OUT + col) = v1;
        }
    }
}

// ---------------------------------------------------------------------------
// Launch.  Inputs: x(f32), qweight(i32), qzeros(i32), scales(f32), g_idx(i32),
//                  bias(f32).  Output f32 [M_TOK, N_OUT].
// ---------------------------------------------------------------------------
extern "C" void kernel_launch(void* const* d_in, const int* in_sizes, int n_in,
                              void* d_out, int out_size)
{
    const float* x       = (const float*)d_in[0];
    const int*   qweight = (const int*)d_in[1];
    const int*   qzeros  = (const int*)d_in[2];
    const float* scales  = (const float*)d_in[3];
    const float* bias    = (const float*)d_in[5];
    float* out = (float*)d_out;

    {
        size_t n4 = (size_t)M_TOK * K_IN / 4;
        convert_x_kernel<<<(unsigned)((n4 + 255) / 256), 256>>>(x);
    }
    {
        cudaFuncSetAttribute(gemm_q4_kernel,
                             cudaFuncAttributeMaxDynamicSharedMemorySize,
                             SMEM_DYN);
        dim3 grid(M_TOK / BM, N_OUT / BN);   // (32, 86), M fastest
        gemm_q4_kernel<<<grid, NTHREADS, SMEM_DYN>>>(qweight, qzeros, scales, bias, out);
    }
}